// round 2
// baseline (speedup 1.0000x reference)
#include <cuda_runtime.h>

#define NV 100000
#define NE 1600000
#define HID 64
#define FIN 256
#define TM 32

// ---------------- scratch (static device globals: no allocation) ------------
__device__ float g_ns[NV];                    // out-degree -> rsqrt norm (src side)
__device__ float g_nd[NV];                    // in-degree  -> rsqrt norm (dst side)
__device__ float g_hs[(size_t)NV * HID];      // per-layer message table (ns * h @ W)
__device__ float g_agg[(size_t)NV * HID];     // scatter destination
__device__ float g_y[(size_t)NV * HID];       // accumulated out @ Wout (pre-aggregation)

// ---------------- small utility kernels -------------------------------------
__global__ void k_zero_norms() {
    int i = blockIdx.x * blockDim.x + threadIdx.x;
    if (i < NV) { g_ns[i] = 0.f; g_nd[i] = 0.f; }
}

__global__ void k_deg(const int* __restrict__ src, const int* __restrict__ dst) {
    int e = blockIdx.x * blockDim.x + threadIdx.x;
    if (e < NE) {
        atomicAdd(&g_ns[src[e]], 1.f);
        atomicAdd(&g_nd[dst[e]], 1.f);
    }
}

__global__ void k_norm() {
    int i = blockIdx.x * blockDim.x + threadIdx.x;
    if (i < NV) {
        g_ns[i] = rsqrtf(fmaxf(g_ns[i], 1.f));
        g_nd[i] = rsqrtf(fmaxf(g_nd[i], 1.f));
    }
}

__global__ void k_zero_agg() {
    int i = blockIdx.x * blockDim.x + threadIdx.x;
    if (i < NV * HID / 4)
        reinterpret_cast<float4*>(g_agg)[i] = make_float4(0.f, 0.f, 0.f, 0.f);
}

__global__ void k_zero_y() {
    int i = blockIdx.x * blockDim.x + threadIdx.x;
    if (i < NV * HID / 4)
        reinterpret_cast<float4*>(g_y)[i] = make_float4(0.f, 0.f, 0.f, 0.f);
}

__global__ void k_init_out(float* __restrict__ out, const float* __restrict__ bout) {
    int i = blockIdx.x * blockDim.x + threadIdx.x;   // float4 index
    if (i < NV * (HID / 4)) {
        float4 b = reinterpret_cast<const float4*>(bout)[i & 15];
        reinterpret_cast<float4*>(out)[i] = b;
    }
}

// ---------------- edge scatter (gather 64f from table, red.v4 into dst) -----
__device__ __forceinline__ void red_add_v4(float* p, float4 v) {
    asm volatile("red.global.add.v4.f32 [%0], {%1,%2,%3,%4};"
                 :: "l"(p), "f"(v.x), "f"(v.y), "f"(v.z), "f"(v.w) : "memory");
}

__global__ void __launch_bounds__(256)
k_scatter_hs(const int* __restrict__ src, const int* __restrict__ dst) {
    unsigned tid = blockIdx.x * blockDim.x + threadIdx.x;   // NE*16 threads
    unsigned e = tid >> 4;
    unsigned c = (tid & 15u) << 2;
    if (e >= NE) return;
    int s = __ldg(src + e);
    int d = __ldg(dst + e);
    float4 v = *reinterpret_cast<const float4*>(g_hs + (size_t)s * HID + c);
    red_add_v4(g_agg + (size_t)d * HID + c, v);
}

__global__ void __launch_bounds__(256)
k_scatter_y(const int* __restrict__ src, const int* __restrict__ dst,
            float* __restrict__ out) {
    unsigned tid = blockIdx.x * blockDim.x + threadIdx.x;
    unsigned e = tid >> 4;
    unsigned c = (tid & 15u) << 2;
    if (e >= NE) return;
    int s = __ldg(src + e);
    int d = __ldg(dst + e);
    float4 v = *reinterpret_cast<const float4*>(g_y + (size_t)s * HID + c);
    red_add_v4(out + (size_t)d * HID + c, v);
}

// ---------------- GEMM 0: hs = ns * (feats @ W0), K=256 ---------------------
// block 128 threads, tile 32 rows x 64 cols, K chunks of 64
__global__ void __launch_bounds__(128)
k_gemm0(const float* __restrict__ feats, const float* __restrict__ W0) {
    __shared__ float As[TM][64];
    __shared__ float Bs[64][64];
    int t = threadIdx.x;
    int tx = t & 15, ty = t >> 4;
    int c0 = tx * 4, m0 = ty * 4;
    int rowBase = blockIdx.x * TM;

    float acc[4][4] = {};
    for (int kb = 0; kb < FIN; kb += 64) {
        #pragma unroll
        for (int i = 0; i < 4; i++) {              // A tile: 32x64
            int f4 = t + i * 128;
            int m = f4 >> 4, k4 = (f4 & 15) * 4;
            *reinterpret_cast<float4*>(&As[m][k4]) =
                *reinterpret_cast<const float4*>(feats + (size_t)(rowBase + m) * FIN + kb + k4);
        }
        #pragma unroll
        for (int i = 0; i < 8; i++) {              // B tile: 64x64
            int f4 = t + i * 128;
            int k = f4 >> 4, c4 = (f4 & 15) * 4;
            *reinterpret_cast<float4*>(&Bs[k][c4]) =
                *reinterpret_cast<const float4*>(W0 + (size_t)(kb + k) * HID + c4);
        }
        __syncthreads();
        #pragma unroll 16
        for (int k = 0; k < 64; k++) {
            float a[4];
            #pragma unroll
            for (int i = 0; i < 4; i++) a[i] = As[m0 + i][k];
            float4 b4 = *reinterpret_cast<const float4*>(&Bs[k][c0]);
            float b[4] = {b4.x, b4.y, b4.z, b4.w};
            #pragma unroll
            for (int i = 0; i < 4; i++)
                #pragma unroll
                for (int j = 0; j < 4; j++)
                    acc[i][j] += a[i] * b[j];
        }
        __syncthreads();
    }
    #pragma unroll
    for (int i = 0; i < 4; i++) {
        int row = rowBase + m0 + i;
        float s = g_ns[row];
        float4 o = make_float4(acc[i][0] * s, acc[i][1] * s, acc[i][2] * s, acc[i][3] * s);
        *reinterpret_cast<float4*>(g_hs + (size_t)row * HID + c0) = o;
    }
}

// ---------------- fused layer GEMM ------------------------------------------
// A = relu(agg * nd + bias)   (materialized only in SMEM)
// if hasW:  hs = ns * (A @ W)      (next layer's messages)
// always:   y += A @ Wo            (JK-cat folded into Wout chunk)
__global__ void __launch_bounds__(128)
k_gemm_fused(const float* __restrict__ bias,
             const float* __restrict__ W,
             const float* __restrict__ Wo,
             int hasW) {
    __shared__ float As[TM][64];
    __shared__ float Bw[64][64];
    __shared__ float Bo[64][64];
    int t = threadIdx.x;
    int tx = t & 15, ty = t >> 4;
    int c0 = tx * 4, m0 = ty * 4;
    int rowBase = blockIdx.x * TM;

    // A tile with relu(agg*nd + b) transform
    #pragma unroll
    for (int i = 0; i < 4; i++) {
        int f4 = t + i * 128;
        int m = f4 >> 4, k4 = (f4 & 15) * 4;
        int row = rowBase + m;
        float4 v = *reinterpret_cast<const float4*>(g_agg + (size_t)row * HID + k4);
        float nd = g_nd[row];
        float4 bb = *reinterpret_cast<const float4*>(bias + k4);
        float4 a;
        a.x = fmaxf(v.x * nd + bb.x, 0.f);
        a.y = fmaxf(v.y * nd + bb.y, 0.f);
        a.z = fmaxf(v.z * nd + bb.z, 0.f);
        a.w = fmaxf(v.w * nd + bb.w, 0.f);
        *reinterpret_cast<float4*>(&As[m][k4]) = a;
    }
    if (hasW) {
        #pragma unroll
        for (int i = 0; i < 8; i++) {
            int f4 = t + i * 128;
            int k = f4 >> 4, c4 = (f4 & 15) * 4;
            *reinterpret_cast<float4*>(&Bw[k][c4]) =
                *reinterpret_cast<const float4*>(W + (size_t)k * HID + c4);
        }
    }
    #pragma unroll
    for (int i = 0; i < 8; i++) {
        int f4 = t + i * 128;
        int k = f4 >> 4, c4 = (f4 & 15) * 4;
        *reinterpret_cast<float4*>(&Bo[k][c4]) =
            *reinterpret_cast<const float4*>(Wo + (size_t)k * HID + c4);
    }
    __syncthreads();

    float accw[4][4] = {};
    float acco[4][4] = {};
    if (hasW) {
        #pragma unroll 16
        for (int k = 0; k < 64; k++) {
            float a[4];
            #pragma unroll
            for (int i = 0; i < 4; i++) a[i] = As[m0 + i][k];
            float4 bw4 = *reinterpret_cast<const float4*>(&Bw[k][c0]);
            float4 bo4 = *reinterpret_cast<const float4*>(&Bo[k][c0]);
            float bw[4] = {bw4.x, bw4.y, bw4.z, bw4.w};
            float bo[4] = {bo4.x, bo4.y, bo4.z, bo4.w};
            #pragma unroll
            for (int i = 0; i < 4; i++)
                #pragma unroll
                for (int j = 0; j < 4; j++) {
                    accw[i][j] += a[i] * bw[j];
                    acco[i][j] += a[i] * bo[j];
                }
        }
    } else {
        #pragma unroll 16
        for (int k = 0; k < 64; k++) {
            float a[4];
            #pragma unroll
            for (int i = 0; i < 4; i++) a[i] = As[m0 + i][k];
            float4 bo4 = *reinterpret_cast<const float4*>(&Bo[k][c0]);
            float bo[4] = {bo4.x, bo4.y, bo4.z, bo4.w};
            #pragma unroll
            for (int i = 0; i < 4; i++)
                #pragma unroll
                for (int j = 0; j < 4; j++)
                    acco[i][j] += a[i] * bo[j];
        }
    }

    #pragma unroll
    for (int i = 0; i < 4; i++) {
        int row = rowBase + m0 + i;
        if (hasW) {
            float s = g_ns[row];
            float4 o = make_float4(accw[i][0] * s, accw[i][1] * s,
                                   accw[i][2] * s, accw[i][3] * s);
            *reinterpret_cast<float4*>(g_hs + (size_t)row * HID + c0) = o;
        }
        float4* yp = reinterpret_cast<float4*>(g_y + (size_t)row * HID + c0);
        float4 yv = *yp;
        yv.x += acco[i][0]; yv.y += acco[i][1];
        yv.z += acco[i][2]; yv.w += acco[i][3];
        *yp = yv;
    }
}

// ---------------- launch ------------------------------------------------------
extern "C" void kernel_launch(void* const* d_in, const int* in_sizes, int n_in,
                              void* d_out, int out_size) {
    const float* feats = (const float*)d_in[0];
    const int*   src   = (const int*)d_in[1];
    const int*   dst   = (const int*)d_in[2];
    const float* W[5];
    const float* B[5];
    for (int i = 0; i < 5; i++) {
        W[i] = (const float*)d_in[3 + 2 * i];
        B[i] = (const float*)d_in[4 + 2 * i];
    }
    const float* Wout = (const float*)d_in[13];
    const float* bout = (const float*)d_in[14];
    float* out = (float*)d_out;

    const int TPB = 256;

    // degrees -> norms
    k_zero_norms<<<(NV + TPB - 1) / TPB, TPB>>>();
    k_deg<<<(NE + TPB - 1) / TPB, TPB>>>(src, dst);
    k_norm<<<(NV + TPB - 1) / TPB, TPB>>>();

    k_zero_y<<<(NV * 16 + TPB - 1) / TPB, TPB>>>();

    // layer 0 projection: hs = ns * (feats @ W0)
    k_gemm0<<<NV / TM, 128>>>(feats, W[0]);

    // 5 message-passing layers
    for (int l = 0; l < 5; l++) {
        k_zero_agg<<<(NV * 16 + TPB - 1) / TPB, TPB>>>();
        k_scatter_hs<<<(NE * 16) / TPB, TPB>>>(src, dst);
        int hasW = (l < 4) ? 1 : 0;
        k_gemm_fused<<<NV / TM, 128>>>(B[l],
                                       hasW ? W[l + 1] : W[0],
                                       Wout + (size_t)l * HID * 64,
                                       hasW);
    }

    // final: out = segment_sum(y[src], dst) + bout
    k_init_out<<<(NV * 16 + TPB - 1) / TPB, TPB>>>(out, bout);
    k_scatter_y<<<(NE * 16) / TPB, TPB>>>(src, dst, out);
}

// round 4
// speedup vs baseline: 1.5827x; 1.5827x over previous
#include <cuda_runtime.h>

#define NV 100000
#define NE 1600000
#define HID 64
#define FIN 256
#define TM 32
#define NBLK_SCAN 391   // ceil(NV/256)

// ---------------- scratch (static device globals) ---------------------------
__device__ float g_ns[NV];
__device__ float g_nd[NV];
__device__ int   g_odeg[NV];
__device__ int   g_indeg[NV];
__device__ int   g_rowptr[NV + 1];
__device__ int   g_cur[NV];
__device__ int   g_bsum[512];
__device__ int   g_boff[512];
__device__ int   g_esrc[NE];                  // src ids grouped by dst (CSR)
__device__ float g_hs[(size_t)NV * HID];      // per-layer message table
__device__ float g_agg[(size_t)NV * HID];     // gather destination
__device__ float g_y[(size_t)NV * HID];       // accumulated out @ Wout

// ---------------- degree / CSR build ----------------------------------------
__global__ void k_zero0() {
    int i = blockIdx.x * blockDim.x + threadIdx.x;
    if (i < NV) { g_odeg[i] = 0; g_indeg[i] = 0; }
}

__global__ void k_deg(const int* __restrict__ src, const int* __restrict__ dst) {
    int e = blockIdx.x * blockDim.x + threadIdx.x;
    if (e < NE) {
        atomicAdd(&g_odeg[src[e]], 1);
        atomicAdd(&g_indeg[dst[e]], 1);
    }
}

// block-level exclusive scan of g_indeg into g_rowptr; block totals to g_bsum
__global__ void __launch_bounds__(256) k_scan1() {
    __shared__ int sm[256];
    int t = threadIdx.x;
    int i = blockIdx.x * 256 + t;
    int v = (i < NV) ? g_indeg[i] : 0;
    sm[t] = v;
    __syncthreads();
    #pragma unroll
    for (int ofs = 1; ofs < 256; ofs <<= 1) {
        int add = (t >= ofs) ? sm[t - ofs] : 0;
        __syncthreads();
        sm[t] += add;
        __syncthreads();
    }
    if (i < NV) g_rowptr[i] = sm[t] - v;          // exclusive, block-local
    if (t == 255) g_bsum[blockIdx.x] = sm[255];
}

__global__ void __launch_bounds__(512) k_scan2() {  // single block
    __shared__ int sm[512];
    int t = threadIdx.x;
    int v = (t < NBLK_SCAN) ? g_bsum[t] : 0;
    sm[t] = v;
    __syncthreads();
    #pragma unroll
    for (int ofs = 1; ofs < 512; ofs <<= 1) {
        int add = (t >= ofs) ? sm[t - ofs] : 0;
        __syncthreads();
        sm[t] += add;
        __syncthreads();
    }
    g_boff[t] = sm[t] - v;       // exclusive block offsets
}

__global__ void k_scan3() {
    int i = blockIdx.x * blockDim.x + threadIdx.x;
    if (i < NV) {
        int r = g_rowptr[i] + g_boff[i >> 8];
        g_rowptr[i] = r;
        g_cur[i] = r;
    }
    if (i == 0) g_rowptr[NV] = NE;
}

__global__ void k_fill(const int* __restrict__ src, const int* __restrict__ dst) {
    int e = blockIdx.x * blockDim.x + threadIdx.x;
    if (e < NE) {
        int pos = atomicAdd(&g_cur[dst[e]], 1);
        g_esrc[pos] = src[e];
    }
}

__global__ void k_norm() {
    int i = blockIdx.x * blockDim.x + threadIdx.x;
    if (i < NV) {
        g_ns[i] = rsqrtf(fmaxf((float)g_odeg[i], 1.f));
        g_nd[i] = rsqrtf(fmaxf((float)g_indeg[i], 1.f));
    }
}

// ---------------- CSR gather: g_agg[n] = sum_{e in in(n)} g_hs[esrc[e]] -----
// one warp per node; lane owns a float2 slice (64 floats = 32 lanes x 2)
__global__ void __launch_bounds__(256)
k_gather_hs() {
    int w = (blockIdx.x * 256 + threadIdx.x) >> 5;
    int lane = threadIdx.x & 31;
    if (w >= NV) return;
    int beg = g_rowptr[w], end = g_rowptr[w + 1];
    const float2* tb = reinterpret_cast<const float2*>(g_hs);
    float2 acc = make_float2(0.f, 0.f);
    int e = beg;
    for (; e + 4 <= end; e += 4) {
        int s0 = g_esrc[e], s1 = g_esrc[e + 1], s2 = g_esrc[e + 2], s3 = g_esrc[e + 3];
        float2 v0 = tb[(size_t)s0 * 32 + lane];
        float2 v1 = tb[(size_t)s1 * 32 + lane];
        float2 v2 = tb[(size_t)s2 * 32 + lane];
        float2 v3 = tb[(size_t)s3 * 32 + lane];
        acc.x += (v0.x + v1.x) + (v2.x + v3.x);
        acc.y += (v0.y + v1.y) + (v2.y + v3.y);
    }
    for (; e < end; e++) {
        int s = g_esrc[e];
        float2 v = tb[(size_t)s * 32 + lane];
        acc.x += v.x; acc.y += v.y;
    }
    reinterpret_cast<float2*>(g_agg)[(size_t)w * 32 + lane] = acc;
}

// final: out[n] = bout + sum_{e in in(n)} g_y[esrc[e]]
__global__ void __launch_bounds__(256)
k_gather_out(float* __restrict__ out, const float* __restrict__ bout) {
    int w = (blockIdx.x * 256 + threadIdx.x) >> 5;
    int lane = threadIdx.x & 31;
    if (w >= NV) return;
    int beg = g_rowptr[w], end = g_rowptr[w + 1];
    const float2* tb = reinterpret_cast<const float2*>(g_y);
    float2 acc = reinterpret_cast<const float2*>(bout)[lane];
    int e = beg;
    for (; e + 4 <= end; e += 4) {
        int s0 = g_esrc[e], s1 = g_esrc[e + 1], s2 = g_esrc[e + 2], s3 = g_esrc[e + 3];
        float2 v0 = tb[(size_t)s0 * 32 + lane];
        float2 v1 = tb[(size_t)s1 * 32 + lane];
        float2 v2 = tb[(size_t)s2 * 32 + lane];
        float2 v3 = tb[(size_t)s3 * 32 + lane];
        acc.x += (v0.x + v1.x) + (v2.x + v3.x);
        acc.y += (v0.y + v1.y) + (v2.y + v3.y);
    }
    for (; e < end; e++) {
        int s = g_esrc[e];
        float2 v = tb[(size_t)s * 32 + lane];
        acc.x += v.x; acc.y += v.y;
    }
    reinterpret_cast<float2*>(out)[(size_t)w * 32 + lane] = acc;
}

// ---------------- GEMM 0: hs = ns * (feats @ W0), K=256 ---------------------
__global__ void __launch_bounds__(128)
k_gemm0(const float* __restrict__ feats, const float* __restrict__ W0) {
    __shared__ float As[TM][64];
    __shared__ float Bs[64][64];
    int t = threadIdx.x;
    int tx = t & 15, ty = t >> 4;
    int c0 = tx * 4, m0 = ty * 4;
    int rowBase = blockIdx.x * TM;

    float acc[4][4] = {};
    for (int kb = 0; kb < FIN; kb += 64) {
        #pragma unroll
        for (int i = 0; i < 4; i++) {
            int f4 = t + i * 128;
            int m = f4 >> 4, k4 = (f4 & 15) * 4;
            *reinterpret_cast<float4*>(&As[m][k4]) =
                *reinterpret_cast<const float4*>(feats + (size_t)(rowBase + m) * FIN + kb + k4);
        }
        #pragma unroll
        for (int i = 0; i < 8; i++) {
            int f4 = t + i * 128;
            int k = f4 >> 4, c4 = (f4 & 15) * 4;
            *reinterpret_cast<float4*>(&Bs[k][c4]) =
                *reinterpret_cast<const float4*>(W0 + (size_t)(kb + k) * HID + c4);
        }
        __syncthreads();
        #pragma unroll 16
        for (int k = 0; k < 64; k++) {
            float a[4];
            #pragma unroll
            for (int i = 0; i < 4; i++) a[i] = As[m0 + i][k];
            float4 b4 = *reinterpret_cast<const float4*>(&Bs[k][c0]);
            float b[4] = {b4.x, b4.y, b4.z, b4.w};
            #pragma unroll
            for (int i = 0; i < 4; i++)
                #pragma unroll
                for (int j = 0; j < 4; j++)
                    acc[i][j] += a[i] * b[j];
        }
        __syncthreads();
    }
    #pragma unroll
    for (int i = 0; i < 4; i++) {
        int row = rowBase + m0 + i;
        float s = g_ns[row];
        float4 o = make_float4(acc[i][0] * s, acc[i][1] * s, acc[i][2] * s, acc[i][3] * s);
        *reinterpret_cast<float4*>(g_hs + (size_t)row * HID + c0) = o;
    }
}

// ---------------- fused layer GEMM ------------------------------------------
// A = relu(agg * nd + bias)   (SMEM only)
// if hasW:   hs = ns * (A @ W)
// firstY=1:  y  = A @ Wo       else  y += A @ Wo
__global__ void __launch_bounds__(128)
k_gemm_fused(const float* __restrict__ bias,
             const float* __restrict__ W,
             const float* __restrict__ Wo,
             int hasW, int firstY) {
    __shared__ float As[TM][64];
    __shared__ float Bw[64][64];
    __shared__ float Bo[64][64];
    int t = threadIdx.x;
    int tx = t & 15, ty = t >> 4;
    int c0 = tx * 4, m0 = ty * 4;
    int rowBase = blockIdx.x * TM;

    #pragma unroll
    for (int i = 0; i < 4; i++) {
        int f4 = t + i * 128;
        int m = f4 >> 4, k4 = (f4 & 15) * 4;
        int row = rowBase + m;
        float4 v = *reinterpret_cast<const float4*>(g_agg + (size_t)row * HID + k4);
        float nd = g_nd[row];
        float4 bb = *reinterpret_cast<const float4*>(bias + k4);
        float4 a;
        a.x = fmaxf(v.x * nd + bb.x, 0.f);
        a.y = fmaxf(v.y * nd + bb.y, 0.f);
        a.z = fmaxf(v.z * nd + bb.z, 0.f);
        a.w = fmaxf(v.w * nd + bb.w, 0.f);
        *reinterpret_cast<float4*>(&As[m][k4]) = a;
    }
    if (hasW) {
        #pragma unroll
        for (int i = 0; i < 8; i++) {
            int f4 = t + i * 128;
            int k = f4 >> 4, c4 = (f4 & 15) * 4;
            *reinterpret_cast<float4*>(&Bw[k][c4]) =
                *reinterpret_cast<const float4*>(W + (size_t)k * HID + c4);
        }
    }
    #pragma unroll
    for (int i = 0; i < 8; i++) {
        int f4 = t + i * 128;
        int k = f4 >> 4, c4 = (f4 & 15) * 4;
        *reinterpret_cast<float4*>(&Bo[k][c4]) =
            *reinterpret_cast<const float4*>(Wo + (size_t)k * HID + c4);
    }
    __syncthreads();

    float accw[4][4] = {};
    float acco[4][4] = {};
    if (hasW) {
        #pragma unroll 16
        for (int k = 0; k < 64; k++) {
            float a[4];
            #pragma unroll
            for (int i = 0; i < 4; i++) a[i] = As[m0 + i][k];
            float4 bw4 = *reinterpret_cast<const float4*>(&Bw[k][c0]);
            float4 bo4 = *reinterpret_cast<const float4*>(&Bo[k][c0]);
            float bw[4] = {bw4.x, bw4.y, bw4.z, bw4.w};
            float bo[4] = {bo4.x, bo4.y, bo4.z, bo4.w};
            #pragma unroll
            for (int i = 0; i < 4; i++)
                #pragma unroll
                for (int j = 0; j < 4; j++) {
                    accw[i][j] += a[i] * bw[j];
                    acco[i][j] += a[i] * bo[j];
                }
        }
    } else {
        #pragma unroll 16
        for (int k = 0; k < 64; k++) {
            float a[4];
            #pragma unroll
            for (int i = 0; i < 4; i++) a[i] = As[m0 + i][k];
            float4 bo4 = *reinterpret_cast<const float4*>(&Bo[k][c0]);
            float bo[4] = {bo4.x, bo4.y, bo4.z, bo4.w};
            #pragma unroll
            for (int i = 0; i < 4; i++)
                #pragma unroll
                for (int j = 0; j < 4; j++)
                    acco[i][j] += a[i] * bo[j];
        }
    }

    #pragma unroll
    for (int i = 0; i < 4; i++) {
        int row = rowBase + m0 + i;
        if (hasW) {
            float s = g_ns[row];
            float4 o = make_float4(accw[i][0] * s, accw[i][1] * s,
                                   accw[i][2] * s, accw[i][3] * s);
            *reinterpret_cast<float4*>(g_hs + (size_t)row * HID + c0) = o;
        }
        float4* yp = reinterpret_cast<float4*>(g_y + (size_t)row * HID + c0);
        if (firstY) {
            *yp = make_float4(acco[i][0], acco[i][1], acco[i][2], acco[i][3]);
        } else {
            float4 yv = *yp;
            yv.x += acco[i][0]; yv.y += acco[i][1];
            yv.z += acco[i][2]; yv.w += acco[i][3];
            *yp = yv;
        }
    }
}

// ---------------- launch ------------------------------------------------------
extern "C" void kernel_launch(void* const* d_in, const int* in_sizes, int n_in,
                              void* d_out, int out_size) {
    const float* feats = (const float*)d_in[0];
    const int*   src   = (const int*)d_in[1];
    const int*   dst   = (const int*)d_in[2];
    const float* W[5];
    const float* B[5];
    for (int i = 0; i < 5; i++) {
        W[i] = (const float*)d_in[3 + 2 * i];
        B[i] = (const float*)d_in[4 + 2 * i];
    }
    const float* Wout = (const float*)d_in[13];
    const float* bout = (const float*)d_in[14];
    float* out = (float*)d_out;

    const int TPB = 256;
    const int NB_V = (NV + TPB - 1) / TPB;      // 391
    const int NB_E = (NE + TPB - 1) / TPB;      // 6250
    const int NB_G = (NV * 32 + TPB - 1) / TPB; // 12500 (warp per node)

    // CSR build + norms
    k_zero0<<<NB_V, TPB>>>();
    k_deg<<<NB_E, TPB>>>(src, dst);
    k_scan1<<<NB_V, 256>>>();
    k_scan2<<<1, 512>>>();
    k_scan3<<<NB_V, TPB>>>();
    k_fill<<<NB_E, TPB>>>(src, dst);
    k_norm<<<NB_V, TPB>>>();

    // layer 0 projection
    k_gemm0<<<NV / TM, 128>>>(feats, W[0]);

    // 5 message-passing layers (CSR gather, no atomics, no zero-fills)
    for (int l = 0; l < 5; l++) {
        k_gather_hs<<<NB_G, TPB>>>();
        int hasW = (l < 4) ? 1 : 0;
        k_gemm_fused<<<NV / TM, 128>>>(B[l],
                                       hasW ? W[l + 1] : W[0],
                                       Wout + (size_t)l * HID * 64,
                                       hasW, l == 0 ? 1 : 0);
    }

    // final aggregation straight into out (+bout)
    k_gather_out<<<NB_G, TPB>>>(out, bout);
}